// round 10
// baseline (speedup 1.0000x reference)
#include <cuda_runtime.h>
#include <math.h>
#include <stdint.h>

#define NTOK 8192
#define DIN  1024
#define NEXP 8
#define HID  4096
#define OUTD 1024
#define GH   4096

// ---------------- scratch ----------------
__device__ float g_h1 [(size_t)NTOK * GH];
__device__ float g_h2 [(size_t)NTOK * DIN];
__device__ float g_hid [(size_t)NEXP * NTOK * HID];
__device__ int   g_cnt [NEXP];
__device__ int   g_list[NEXP * NTOK];
__device__ float g_wl  [NEXP * NTOK];

__device__ __forceinline__ float tf32r(float x) {
    float r; asm("cvt.rna.tf32.f32 %0, %1;" : "=f"(r) : "f"(x)); return r;
}
__device__ __forceinline__ uint32_t cvta_s(const void* p) {
    uint32_t a;
    asm("{ .reg .u64 t; cvta.to.shared.u64 t, %1; cvt.u32.u64 %0, t; }" : "=r"(a) : "l"(p));
    return a;
}
#define CP16(d, s)  asm volatile("cp.async.ca.shared.global [%0], [%1], 16;" :: "r"(d), "l"(s))
#define CPCOMMIT()  asm volatile("cp.async.commit_group;" ::: "memory")
#define CPWAIT1()   asm volatile("cp.async.wait_group 1;" ::: "memory")

__device__ __forceinline__ void mma_tf32(float* c, const uint32_t* a, const uint32_t* b) {
    asm volatile(
        "mma.sync.aligned.m16n8k8.row.col.f32.tf32.tf32.f32 "
        "{%0,%1,%2,%3}, {%4,%5,%6,%7}, {%8,%9}, {%0,%1,%2,%3};\n"
        : "+f"(c[0]), "+f"(c[1]), "+f"(c[2]), "+f"(c[3])
        : "r"(a[0]), "r"(a[1]), "r"(a[2]), "r"(a[3]), "r"(b[0]), "r"(b[1]));
}
__device__ __forceinline__ void mma_bf16(float* c, const uint32_t* a, const uint32_t* b) {
    asm volatile(
        "mma.sync.aligned.m16n8k16.row.col.f32.bf16.bf16.f32 "
        "{%0,%1,%2,%3}, {%4,%5,%6,%7}, {%8,%9}, {%0,%1,%2,%3};\n"
        : "+f"(c[0]), "+f"(c[1]), "+f"(c[2]), "+f"(c[3])
        : "r"(a[0]), "r"(a[1]), "r"(a[2]), "r"(a[3]), "r"(b[0]), "r"(b[1]));
}
// exact 2-way bf16 split of a pair: hi = trunc16(v), mid holds residual; packed (x=lo, y=hi)
__device__ __forceinline__ void split2(float x, float y, uint32_t& hi, uint32_t& mid) {
    uint32_t ux = __float_as_uint(x), uy = __float_as_uint(y);
    hi = __byte_perm(ux, uy, 0x7632);
    float rx = x - __uint_as_float(ux & 0xFFFF0000u);
    float ry = y - __uint_as_float(uy & 0xFFFF0000u);
    mid = __byte_perm(__float_as_uint(rx), __float_as_uint(ry), 0x7632);
}

// SMEM per stage: A raw [128 rows][20 floats], B raw [16 k][BSTR n]
#define A_STRIDE 20
#define A_PLANE  (128 * A_STRIDE)          // 2560 floats
#define STAGE_F  (A_PLANE + 16 * 136)      // 4736 floats (max of both modes)
#define NSTAGE   6
#define SMEM_BYTES (NSTAGE * STAGE_F * 4)  // 113664

// ---------------- reset / zero ----------------
__global__ void reset_kernel() {
    if (threadIdx.x < NEXP) g_cnt[threadIdx.x] = 0;
}
__global__ void zero_y_kernel(float* __restrict__ y) {
    const size_t i = (size_t)blockIdx.x * blockDim.x + threadIdx.x;
    *(float4*)(y + i * 4) = make_float4(0.f, 0.f, 0.f, 0.f);
}

// ---------------- GEMM: C = (A @ B + bias)[relu], B row-major [K,N] ----------------
// MODE 0: tf32 3-term (gates).  MODE 1: bf16 2-split 3-MMA (experts).
// listA: gather map for A rows (slot -> token); nullptr = identity.
// listS + wl: fused scatter epilogue  y[listS[slot]] += wl[slot] * (acc + bias).
template<int MODE>
__global__ __launch_bounds__(256) void gemm_tc(
    const float* __restrict__ A, size_t sAe,
    const float* __restrict__ B, size_t sBe,
    const float* __restrict__ bias, size_t sBiasE,
    float* __restrict__ C, size_t sCe,
    int K, int N, int doRelu,
    const int* __restrict__ listA, const int* __restrict__ cntArr,
    const int* __restrict__ listS, const float* __restrict__ wl)
{
    const int BSTR = MODE ? 132 : 136;
    const int e   = blockIdx.z;
    const int cnt = cntArr ? cntArr[e] : (int)(gridDim.y * 128);
    const int m0  = blockIdx.y * 128;
    if (m0 >= cnt) return;
    const int n0  = blockIdx.x * 128;

    extern __shared__ float smem[];
    const uint32_t sbase = cvta_s(smem);

    const int tid  = threadIdx.x;
    const int wid  = tid >> 5;
    const int lane = tid & 31;
    const int wm0  = (wid >> 2) * 64;
    const int wn0  = (wid & 3) * 32;

    int arow = m0 + (tid >> 1); if (arow > cnt - 1) arow = cnt - 1;
    if (listA) arow = listA[e * NTOK + arow];
    const int acol = (tid & 1) * 8;
    const float* Ap = A + sAe * e + (size_t)arow * K + acol;
    const int bk = tid >> 4;
    const int bn = (tid & 15) * 8;
    const float* Bp = B + sBe * e + (size_t)bk * N + n0 + bn;
    const uint32_t adst0 = sbase + (uint32_t)((tid >> 1) * A_STRIDE + acol) * 4u;
    const uint32_t bdst0 = sbase + (uint32_t)(A_PLANE + bk * BSTR + bn) * 4u;

    const int T = K >> 4;   // even for all our K

    auto issue = [&](int kt) {
        const int s = kt % NSTAGE;
        const float* ap = Ap + kt * 16;
        uint32_t ad = adst0 + (uint32_t)(s * STAGE_F) * 4u;
        CP16(ad,      ap);
        CP16(ad + 16, ap + 4);
        const float* bp = Bp + (size_t)kt * 16 * N;
        uint32_t bd = bdst0 + (uint32_t)(s * STAGE_F) * 4u;
        CP16(bd,      bp);
        CP16(bd + 16, bp + 4);
    };

    float acc[4][4][4];
    #pragma unroll
    for (int im = 0; im < 4; im++)
        #pragma unroll
        for (int jn = 0; jn < 4; jn++)
            #pragma unroll
            for (int q = 0; q < 4; q++) acc[im][jn][q] = 0.f;

    // prologue: two committed groups of two chunks each
    issue(0); if (T > 1) issue(1); CPCOMMIT();
    if (T > 2) { issue(2); issue(3); } CPCOMMIT();

    const int fr = lane >> 2;
    const int fk = lane & 3;

    auto compute_chunk = [&](int kt) {
        const int s = kt % NSTAGE;
        const float* As_ = smem + s * STAGE_F;
        const float* Bs_ = smem + s * STAGE_F + A_PLANE;
        if (MODE == 1) {
            const int k2 = fk * 2;
            uint32_t ah[4][4], am[4][4];
            #pragma unroll
            for (int im = 0; im < 4; im++) {
                const int m = wm0 + im * 16 + fr;
                float2 v00 = *(const float2*)&As_[m * A_STRIDE + k2];
                float2 v10 = *(const float2*)&As_[(m + 8) * A_STRIDE + k2];
                float2 v01 = *(const float2*)&As_[m * A_STRIDE + k2 + 8];
                float2 v11 = *(const float2*)&As_[(m + 8) * A_STRIDE + k2 + 8];
                split2(v00.x, v00.y, ah[im][0], am[im][0]);
                split2(v10.x, v10.y, ah[im][1], am[im][1]);
                split2(v01.x, v01.y, ah[im][2], am[im][2]);
                split2(v11.x, v11.y, ah[im][3], am[im][3]);
            }
            uint32_t bh[4][2], bm[4][2];
            #pragma unroll
            for (int jn = 0; jn < 4; jn++) {
                const int n = wn0 + jn * 8 + fr;
                float b0 = Bs_[(k2)     * BSTR + n];
                float b1 = Bs_[(k2 + 1) * BSTR + n];
                float b2 = Bs_[(k2 + 8) * BSTR + n];
                float b3 = Bs_[(k2 + 9) * BSTR + n];
                split2(b0, b1, bh[jn][0], bm[jn][0]);
                split2(b2, b3, bh[jn][1], bm[jn][1]);
            }
            #pragma unroll
            for (int im = 0; im < 4; im++)
                #pragma unroll
                for (int jn = 0; jn < 4; jn++)
                    mma_bf16(acc[im][jn], ah[im], bh[jn]);
            #pragma unroll
            for (int im = 0; im < 4; im++)
                #pragma unroll
                for (int jn = 0; jn < 4; jn++)
                    mma_bf16(acc[im][jn], ah[im], bm[jn]);
            #pragma unroll
            for (int im = 0; im < 4; im++)
                #pragma unroll
                for (int jn = 0; jn < 4; jn++)
                    mma_bf16(acc[im][jn], am[im], bh[jn]);
        } else {
            #pragma unroll
            for (int ks = 0; ks < 16; ks += 8) {
                const int k = ks + fk;
                float arw[4][4];
                #pragma unroll
                for (int im = 0; im < 4; im++) {
                    const int m = wm0 + im * 16 + fr;
                    arw[im][0] = As_[m * A_STRIDE + k];
                    arw[im][1] = As_[(m + 8) * A_STRIDE + k];
                    arw[im][2] = As_[m * A_STRIDE + k + 4];
                    arw[im][3] = As_[(m + 8) * A_STRIDE + k + 4];
                }
                float brw[4][2];
                #pragma unroll
                for (int jn = 0; jn < 4; jn++) {
                    const int n = wn0 + jn * 8 + fr;
                    brw[jn][0] = Bs_[k * BSTR + n];
                    brw[jn][1] = Bs_[(k + 4) * BSTR + n];
                }
                uint32_t ah[4][4], al[4][4], bh[4][2], bl[4][2];
                #pragma unroll
                for (int im = 0; im < 4; im++)
                    #pragma unroll
                    for (int q = 0; q < 4; q++) {
                        float h = tf32r(arw[im][q]);
                        ah[im][q] = __float_as_uint(h);
                        al[im][q] = __float_as_uint(arw[im][q] - h);
                    }
                #pragma unroll
                for (int jn = 0; jn < 4; jn++)
                    #pragma unroll
                    for (int q = 0; q < 2; q++) {
                        float h = tf32r(brw[jn][q]);
                        bh[jn][q] = __float_as_uint(h);
                        bl[jn][q] = __float_as_uint(brw[jn][q] - h);
                    }
                #pragma unroll
                for (int im = 0; im < 4; im++)
                    #pragma unroll
                    for (int jn = 0; jn < 4; jn++)
                        mma_tf32(acc[im][jn], ah[im], bh[jn]);
                #pragma unroll
                for (int im = 0; im < 4; im++)
                    #pragma unroll
                    for (int jn = 0; jn < 4; jn++)
                        mma_tf32(acc[im][jn], ah[im], bl[jn]);
                #pragma unroll
                for (int im = 0; im < 4; im++)
                    #pragma unroll
                    for (int jn = 0; jn < 4; jn++)
                        mma_tf32(acc[im][jn], al[im], bh[jn]);
            }
        }
    };

    for (int kt = 0; kt < T; kt += 2) {
        CPWAIT1();
        __syncthreads();
        // stages (kt+4)%6,(kt+5)%6 were consumed before the sync; safe to overwrite
        if (kt + 4 < T) { issue(kt + 4); if (kt + 5 < T) issue(kt + 5); }
        CPCOMMIT();
        compute_chunk(kt);
        if (kt + 1 < T) compute_chunk(kt + 1);
    }

    // ---- epilogue ----
    const float* bp = bias + sBiasE * e + n0;
    if (wl == nullptr) {
        float* Cbase = C + sCe * e;
        #pragma unroll
        for (int im = 0; im < 4; im++) {
            #pragma unroll
            for (int half = 0; half < 2; half++) {
                const int rr = m0 + wm0 + im * 16 + (lane >> 2) + half * 8;
                if (rr < cnt) {
                    float* crow = Cbase + (size_t)rr * N + n0;
                    #pragma unroll
                    for (int jn = 0; jn < 4; jn++) {
                        const int col = wn0 + jn * 8 + (lane & 3) * 2;
                        float v0 = acc[im][jn][half * 2 + 0] + bp[col];
                        float v1 = acc[im][jn][half * 2 + 1] + bp[col + 1];
                        if (doRelu) { v0 = fmaxf(v0, 0.f); v1 = fmaxf(v1, 0.f); }
                        *(float2*)(crow + col) = make_float2(v0, v1);
                    }
                }
            }
        }
    } else {
        // fused combine: y[tok] += w * (acc + bias); exactly 2 adds per element -> deterministic
        #pragma unroll
        for (int im = 0; im < 4; im++) {
            #pragma unroll
            for (int half = 0; half < 2; half++) {
                const int rr = m0 + wm0 + im * 16 + (lane >> 2) + half * 8;
                if (rr < cnt) {
                    const int tok = listS[e * NTOK + rr];
                    const float w = wl[e * NTOK + rr];
                    float* crow = C + (size_t)tok * N + n0;
                    #pragma unroll
                    for (int jn = 0; jn < 4; jn++) {
                        const int col = wn0 + jn * 8 + (lane & 3) * 2;
                        float v0 = w * (acc[im][jn][half * 2 + 0] + bp[col]);
                        float v1 = w * (acc[im][jn][half * 2 + 1] + bp[col + 1]);
                        atomicAdd(crow + col, v0);
                        atomicAdd(crow + col + 1, v1);
                    }
                }
            }
        }
    }
}

// ---------------- routing ----------------
__global__ void route_kernel(const float* __restrict__ h2,
                             const float* __restrict__ G3,
                             const float* __restrict__ g3,
                             float* __restrict__ pout)
{
    const int gw   = (blockIdx.x * blockDim.x + threadIdx.x) >> 5;
    const int lane = threadIdx.x & 31;
    if (gw >= NTOK) return;

    const float* hrow = h2 + (size_t)gw * DIN;
    float acc[8] = {0,0,0,0,0,0,0,0};
    for (int k = lane; k < DIN; k += 32) {
        float hv = hrow[k];
        const float4 ga = *(const float4*)(G3 + k * 8);
        const float4 gb = *(const float4*)(G3 + k * 8 + 4);
        acc[0] += hv * ga.x; acc[1] += hv * ga.y;
        acc[2] += hv * ga.z; acc[3] += hv * ga.w;
        acc[4] += hv * gb.x; acc[5] += hv * gb.y;
        acc[6] += hv * gb.z; acc[7] += hv * gb.w;
    }
    #pragma unroll
    for (int e = 0; e < 8; e++)
        #pragma unroll
        for (int o = 16; o; o >>= 1)
            acc[e] += __shfl_xor_sync(0xffffffffu, acc[e], o);

    if (lane == 0) {
        float lg[8];
        #pragma unroll
        for (int e = 0; e < 8; e++) lg[e] = acc[e] + g3[e];

        int i1 = 0; float v1 = lg[0];
        #pragma unroll
        for (int e = 1; e < 8; e++)
            if (lg[e] > v1) { v1 = lg[e]; i1 = e; }
        int i2 = -1; float v2 = -3.4e38f;
        #pragma unroll
        for (int e = 0; e < 8; e++)
            if (e != i1 && lg[e] > v2) { v2 = lg[e]; i2 = e; }

        float ex = expf(v2 - v1);
        float p1 = 1.f / (1.f + ex);
        float p2 = ex  / (1.f + ex);

        float pr[8] = {0,0,0,0,0,0,0,0};
        pr[i1] = p1; pr[i2] = p2;
        float* prow = pout + (size_t)gw * NEXP;
        *(float4*)prow       = make_float4(pr[0], pr[1], pr[2], pr[3]);
        *(float4*)(prow + 4) = make_float4(pr[4], pr[5], pr[6], pr[7]);

        int s1 = atomicAdd(&g_cnt[i1], 1);
        g_list[i1 * NTOK + s1] = gw;
        g_wl  [i1 * NTOK + s1] = p1;
        int s2 = atomicAdd(&g_cnt[i2], 1);
        g_list[i2 * NTOK + s2] = gw;
        g_wl  [i2 * NTOK + s2] = p2;
    }
}

// ---------------- launch ----------------
extern "C" void kernel_launch(void* const* d_in, const int* in_sizes, int n_in,
                              void* d_out, int out_size)
{
    const float* x  = (const float*)d_in[0];
    const float* W1 = (const float*)d_in[1];
    const float* b1 = (const float*)d_in[2];
    const float* W2 = (const float*)d_in[3];
    const float* b2 = (const float*)d_in[4];
    const float* G1 = (const float*)d_in[5];
    const float* g1 = (const float*)d_in[6];
    const float* G2 = (const float*)d_in[7];
    const float* g2 = (const float*)d_in[8];
    const float* G3 = (const float*)d_in[9];
    const float* g3 = (const float*)d_in[10];

    float* y = (float*)d_out;
    float* p = (float*)d_out + (size_t)NTOK * OUTD;

    void* tmp;
    cudaGetSymbolAddress(&tmp, g_h1);   float* h1  = (float*)tmp;
    cudaGetSymbolAddress(&tmp, g_h2);   float* h2  = (float*)tmp;
    cudaGetSymbolAddress(&tmp, g_hid);  float* hid = (float*)tmp;
    cudaGetSymbolAddress(&tmp, g_list); int*   lst = (int*)tmp;
    cudaGetSymbolAddress(&tmp, g_cnt);  int*   cnt = (int*)tmp;
    cudaGetSymbolAddress(&tmp, g_wl);   float* wl  = (float*)tmp;

    cudaFuncSetAttribute(gemm_tc<0>, cudaFuncAttributeMaxDynamicSharedMemorySize, SMEM_BYTES);
    cudaFuncSetAttribute(gemm_tc<1>, cudaFuncAttributeMaxDynamicSharedMemorySize, SMEM_BYTES);

    reset_kernel<<<1, 32>>>();
    zero_y_kernel<<<(NTOK * OUTD) / (256 * 4), 256>>>(y);

    // gate layer 1: h1 = relu(x @ G1 + g1)   — tf32 3-term (selection-critical)
    gemm_tc<0><<<dim3(GH / 128, NTOK / 128, 1), 256, SMEM_BYTES>>>(
        x, 0, G1, 0, g1, 0, h1, 0, DIN, GH, 1, nullptr, nullptr, nullptr, nullptr);
    // gate layer 2: h2 = relu(h1 @ G2 + g2)  — tf32 3-term
    gemm_tc<0><<<dim3(DIN / 128, NTOK / 128, 1), 256, SMEM_BYTES>>>(
        h1, 0, G2, 0, g2, 0, h2, 0, GH, DIN, 1, nullptr, nullptr, nullptr, nullptr);
    // routing
    route_kernel<<<NTOK / 8, 256>>>(h2, G3, g3, p);
    // expert FFN1: hid[slot] = relu(x[list[slot]] @ W1[e] + b1[e])  — gather A
    gemm_tc<1><<<dim3(HID / 128, NTOK / 128, NEXP), 256, SMEM_BYTES>>>(
        x, 0, W1, (size_t)DIN * HID, b1, HID, hid, (size_t)NTOK * HID,
        DIN, HID, 1, lst, cnt, nullptr, nullptr);
    // expert FFN2 + fused combine: y[list[slot]] += wl[slot] * (hid[slot] @ W2[e] + b2[e])
    // A is identity-indexed (hid is slot-ordered); list used ONLY for the scatter.
    gemm_tc<1><<<dim3(OUTD / 128, NTOK / 128, NEXP), 256, SMEM_BYTES>>>(
        hid, (size_t)NTOK * HID, W2, (size_t)HID * OUTD, b2, OUTD, y, 0,
        HID, OUTD, 0, nullptr, cnt, lst, wl);
}

// round 11
// speedup vs baseline: 1.1809x; 1.1809x over previous
#include <cuda_runtime.h>
#include <math.h>
#include <stdint.h>

#define NTOK 8192
#define DIN  1024
#define NEXP 8
#define HID  4096
#define OUTD 1024
#define GH   4096

// ---------------- scratch ----------------
__device__ float g_h1 [(size_t)NTOK * GH];
__device__ float g_h2 [(size_t)NTOK * DIN];
__device__ float g_hid [(size_t)NEXP * NTOK * HID];
__device__ int   g_cnt [NEXP];
__device__ int   g_list[NEXP * NTOK];
__device__ float g_wl  [NEXP * NTOK];

__device__ __forceinline__ float tf32r(float x) {
    float r; asm("cvt.rna.tf32.f32 %0, %1;" : "=f"(r) : "f"(x)); return r;
}
__device__ __forceinline__ uint32_t cvta_s(const void* p) {
    uint32_t a;
    asm("{ .reg .u64 t; cvta.to.shared.u64 t, %1; cvt.u32.u64 %0, t; }" : "=r"(a) : "l"(p));
    return a;
}
#define CP16(d, s)  asm volatile("cp.async.ca.shared.global [%0], [%1], 16;" :: "r"(d), "l"(s))
#define CPCOMMIT()  asm volatile("cp.async.commit_group;" ::: "memory")
#define CPWAIT1()   asm volatile("cp.async.wait_group 1;" ::: "memory")

__device__ __forceinline__ void mma_tf32(float* c, const uint32_t* a, const uint32_t* b) {
    asm volatile(
        "mma.sync.aligned.m16n8k8.row.col.f32.tf32.tf32.f32 "
        "{%0,%1,%2,%3}, {%4,%5,%6,%7}, {%8,%9}, {%0,%1,%2,%3};\n"
        : "+f"(c[0]), "+f"(c[1]), "+f"(c[2]), "+f"(c[3])
        : "r"(a[0]), "r"(a[1]), "r"(a[2]), "r"(a[3]), "r"(b[0]), "r"(b[1]));
}
__device__ __forceinline__ void mma_bf16(float* c, const uint32_t* a, const uint32_t* b) {
    asm volatile(
        "mma.sync.aligned.m16n8k16.row.col.f32.bf16.bf16.f32 "
        "{%0,%1,%2,%3}, {%4,%5,%6,%7}, {%8,%9}, {%0,%1,%2,%3};\n"
        : "+f"(c[0]), "+f"(c[1]), "+f"(c[2]), "+f"(c[3])
        : "r"(a[0]), "r"(a[1]), "r"(a[2]), "r"(a[3]), "r"(b[0]), "r"(b[1]));
}
// exact 2-way bf16 split of a pair: hi = trunc16(v), mid holds residual; packed (x=lo, y=hi)
__device__ __forceinline__ void split2(float x, float y, uint32_t& hi, uint32_t& mid) {
    uint32_t ux = __float_as_uint(x), uy = __float_as_uint(y);
    hi = __byte_perm(ux, uy, 0x7632);
    float rx = x - __uint_as_float(ux & 0xFFFF0000u);
    float ry = y - __uint_as_float(uy & 0xFFFF0000u);
    mid = __byte_perm(__float_as_uint(rx), __float_as_uint(ry), 0x7632);
}

// SMEM per stage: A raw [128 rows][20 floats], B raw [16 k][BSTR n]
#define A_STRIDE 20
#define A_PLANE  (128 * A_STRIDE)          // 2560 floats
#define STAGE_F  (A_PLANE + 16 * 136)      // 4736 floats (max of both modes)
#define NSTAGE   3
#define SMEM_BYTES (NSTAGE * STAGE_F * 4)  // 56832  -> 2 CTAs/SM

// ---------------- reset / zero ----------------
__global__ void reset_kernel() {
    if (threadIdx.x < NEXP) g_cnt[threadIdx.x] = 0;
}
__global__ void zero_y_kernel(float* __restrict__ y) {
    const size_t i = (size_t)blockIdx.x * blockDim.x + threadIdx.x;
    *(float4*)(y + i * 4) = make_float4(0.f, 0.f, 0.f, 0.f);
}

// ---------------- GEMM: C = (A @ B + bias)[relu], B row-major [K,N] ----------------
// MODE 0: tf32 3-term (gates).  MODE 1: bf16 2-split 3-MMA (experts).
// listA: gather map for A rows (slot -> token); nullptr = identity.
// listS + wl: fused scatter epilogue  y[listS[slot]] += wl[slot] * (acc + bias).
// 256 threads, 8 warps, warp tile 64x32 (2m x 4n), CTA tile 128x128, BK=16, 3-stage ring.
template<int MODE>
__global__ __launch_bounds__(256) void gemm_tc(
    const float* __restrict__ A, size_t sAe,
    const float* __restrict__ B, size_t sBe,
    const float* __restrict__ bias, size_t sBiasE,
    float* __restrict__ C, size_t sCe,
    int K, int N, int doRelu,
    const int* __restrict__ listA, const int* __restrict__ cntArr,
    const int* __restrict__ listS, const float* __restrict__ wl)
{
    const int BSTR = MODE ? 132 : 136;
    const int e   = blockIdx.z;
    const int cnt = cntArr ? cntArr[e] : (int)(gridDim.y * 128);
    const int m0  = blockIdx.y * 128;
    if (m0 >= cnt) return;
    const int n0  = blockIdx.x * 128;

    extern __shared__ float smem[];
    const uint32_t sbase = cvta_s(smem);

    const int tid  = threadIdx.x;
    const int wid  = tid >> 5;
    const int lane = tid & 31;
    const int wm0  = (wid >> 2) * 64;
    const int wn0  = (wid & 3) * 32;

    int arow = m0 + (tid >> 1); if (arow > cnt - 1) arow = cnt - 1;
    if (listA) arow = listA[e * NTOK + arow];
    const int acol = (tid & 1) * 8;
    const float* Ap = A + sAe * e + (size_t)arow * K + acol;
    const int bk = tid >> 4;
    const int bn = (tid & 15) * 8;
    const float* Bp = B + sBe * e + (size_t)bk * N + n0 + bn;
    const uint32_t adst0 = sbase + (uint32_t)((tid >> 1) * A_STRIDE + acol) * 4u;
    const uint32_t bdst0 = sbase + (uint32_t)(A_PLANE + bk * BSTR + bn) * 4u;

    const int T = K >> 4;

    auto issue = [&](int kt) {
        const int s = kt % NSTAGE;
        const float* ap = Ap + kt * 16;
        uint32_t ad = adst0 + (uint32_t)(s * STAGE_F) * 4u;
        CP16(ad,      ap);
        CP16(ad + 16, ap + 4);
        const float* bp = Bp + (size_t)kt * 16 * N;
        uint32_t bd = bdst0 + (uint32_t)(s * STAGE_F) * 4u;
        CP16(bd,      bp);
        CP16(bd + 16, bp + 4);
    };

    float acc[4][4][4];
    #pragma unroll
    for (int im = 0; im < 4; im++)
        #pragma unroll
        for (int jn = 0; jn < 4; jn++)
            #pragma unroll
            for (int q = 0; q < 4; q++) acc[im][jn][q] = 0.f;

    issue(0); CPCOMMIT();
    if (T > 1) issue(1);
    CPCOMMIT();

    const int fr = lane >> 2;
    const int fk = lane & 3;

    for (int kt = 0; kt < T; ++kt) {
        CPWAIT1();
        __syncthreads();
        const int s = kt % NSTAGE;
        const float* As_ = smem + s * STAGE_F;
        const float* Bs_ = smem + s * STAGE_F + A_PLANE;

        if (MODE == 1) {
            const int k2 = fk * 2;
            uint32_t ah[4][4], am[4][4];
            #pragma unroll
            for (int im = 0; im < 4; im++) {
                const int m = wm0 + im * 16 + fr;
                float2 v00 = *(const float2*)&As_[m * A_STRIDE + k2];
                float2 v10 = *(const float2*)&As_[(m + 8) * A_STRIDE + k2];
                float2 v01 = *(const float2*)&As_[m * A_STRIDE + k2 + 8];
                float2 v11 = *(const float2*)&As_[(m + 8) * A_STRIDE + k2 + 8];
                split2(v00.x, v00.y, ah[im][0], am[im][0]);
                split2(v10.x, v10.y, ah[im][1], am[im][1]);
                split2(v01.x, v01.y, ah[im][2], am[im][2]);
                split2(v11.x, v11.y, ah[im][3], am[im][3]);
            }
            uint32_t bh[4][2], bm[4][2];
            #pragma unroll
            for (int jn = 0; jn < 4; jn++) {
                const int n = wn0 + jn * 8 + fr;
                float b0 = Bs_[(k2)     * BSTR + n];
                float b1 = Bs_[(k2 + 1) * BSTR + n];
                float b2 = Bs_[(k2 + 8) * BSTR + n];
                float b3 = Bs_[(k2 + 9) * BSTR + n];
                split2(b0, b1, bh[jn][0], bm[jn][0]);
                split2(b2, b3, bh[jn][1], bm[jn][1]);
            }
            #pragma unroll
            for (int im = 0; im < 4; im++)
                #pragma unroll
                for (int jn = 0; jn < 4; jn++)
                    mma_bf16(acc[im][jn], ah[im], bh[jn]);
            #pragma unroll
            for (int im = 0; im < 4; im++)
                #pragma unroll
                for (int jn = 0; jn < 4; jn++)
                    mma_bf16(acc[im][jn], ah[im], bm[jn]);
            #pragma unroll
            for (int im = 0; im < 4; im++)
                #pragma unroll
                for (int jn = 0; jn < 4; jn++)
                    mma_bf16(acc[im][jn], am[im], bh[jn]);
        } else {
            #pragma unroll
            for (int ks = 0; ks < 16; ks += 8) {
                const int k = ks + fk;
                float arw[4][4];
                #pragma unroll
                for (int im = 0; im < 4; im++) {
                    const int m = wm0 + im * 16 + fr;
                    arw[im][0] = As_[m * A_STRIDE + k];
                    arw[im][1] = As_[(m + 8) * A_STRIDE + k];
                    arw[im][2] = As_[m * A_STRIDE + k + 4];
                    arw[im][3] = As_[(m + 8) * A_STRIDE + k + 4];
                }
                float brw[4][2];
                #pragma unroll
                for (int jn = 0; jn < 4; jn++) {
                    const int n = wn0 + jn * 8 + fr;
                    brw[jn][0] = Bs_[k * BSTR + n];
                    brw[jn][1] = Bs_[(k + 4) * BSTR + n];
                }
                uint32_t ah[4][4], al[4][4], bh[4][2], bl[4][2];
                #pragma unroll
                for (int im = 0; im < 4; im++)
                    #pragma unroll
                    for (int q = 0; q < 4; q++) {
                        float h = tf32r(arw[im][q]);
                        ah[im][q] = __float_as_uint(h);
                        al[im][q] = __float_as_uint(arw[im][q] - h);
                    }
                #pragma unroll
                for (int jn = 0; jn < 4; jn++)
                    #pragma unroll
                    for (int q = 0; q < 2; q++) {
                        float h = tf32r(brw[jn][q]);
                        bh[jn][q] = __float_as_uint(h);
                        bl[jn][q] = __float_as_uint(brw[jn][q] - h);
                    }
                #pragma unroll
                for (int im = 0; im < 4; im++)
                    #pragma unroll
                    for (int jn = 0; jn < 4; jn++)
                        mma_tf32(acc[im][jn], ah[im], bh[jn]);
                #pragma unroll
                for (int im = 0; im < 4; im++)
                    #pragma unroll
                    for (int jn = 0; jn < 4; jn++)
                        mma_tf32(acc[im][jn], ah[im], bl[jn]);
                #pragma unroll
                for (int im = 0; im < 4; im++)
                    #pragma unroll
                    for (int jn = 0; jn < 4; jn++)
                        mma_tf32(acc[im][jn], al[im], bh[jn]);
            }
        }

        if (kt + 2 < T) issue(kt + 2);
        CPCOMMIT();
    }

    // ---- epilogue ----
    const float* bp = bias + sBiasE * e + n0;
    if (wl == nullptr) {
        float* Cbase = C + sCe * e;
        #pragma unroll
        for (int im = 0; im < 4; im++) {
            #pragma unroll
            for (int half = 0; half < 2; half++) {
                const int rr = m0 + wm0 + im * 16 + (lane >> 2) + half * 8;
                if (rr < cnt) {
                    float* crow = Cbase + (size_t)rr * N + n0;
                    #pragma unroll
                    for (int jn = 0; jn < 4; jn++) {
                        const int col = wn0 + jn * 8 + (lane & 3) * 2;
                        float v0 = acc[im][jn][half * 2 + 0] + bp[col];
                        float v1 = acc[im][jn][half * 2 + 1] + bp[col + 1];
                        if (doRelu) { v0 = fmaxf(v0, 0.f); v1 = fmaxf(v1, 0.f); }
                        *(float2*)(crow + col) = make_float2(v0, v1);
                    }
                }
            }
        }
    } else {
        // fused combine: y[tok] += w * (acc + bias); exactly 2 adds per element -> deterministic
        #pragma unroll
        for (int im = 0; im < 4; im++) {
            #pragma unroll
            for (int half = 0; half < 2; half++) {
                const int rr = m0 + wm0 + im * 16 + (lane >> 2) + half * 8;
                if (rr < cnt) {
                    const int tok = listS[e * NTOK + rr];
                    const float w = wl[e * NTOK + rr];
                    float* crow = C + (size_t)tok * N + n0;
                    #pragma unroll
                    for (int jn = 0; jn < 4; jn++) {
                        const int col = wn0 + jn * 8 + (lane & 3) * 2;
                        float v0 = w * (acc[im][jn][half * 2 + 0] + bp[col]);
                        float v1 = w * (acc[im][jn][half * 2 + 1] + bp[col + 1]);
                        atomicAdd(crow + col, v0);
                        atomicAdd(crow + col + 1, v1);
                    }
                }
            }
        }
    }
}

// ---------------- routing ----------------
__global__ void route_kernel(const float* __restrict__ h2,
                             const float* __restrict__ G3,
                             const float* __restrict__ g3,
                             float* __restrict__ pout)
{
    const int gw   = (blockIdx.x * blockDim.x + threadIdx.x) >> 5;
    const int lane = threadIdx.x & 31;
    if (gw >= NTOK) return;

    const float* hrow = h2 + (size_t)gw * DIN;
    float acc[8] = {0,0,0,0,0,0,0,0};
    for (int k = lane; k < DIN; k += 32) {
        float hv = hrow[k];
        const float4 ga = *(const float4*)(G3 + k * 8);
        const float4 gb = *(const float4*)(G3 + k * 8 + 4);
        acc[0] += hv * ga.x; acc[1] += hv * ga.y;
        acc[2] += hv * ga.z; acc[3] += hv * ga.w;
        acc[4] += hv * gb.x; acc[5] += hv * gb.y;
        acc[6] += hv * gb.z; acc[7] += hv * gb.w;
    }
    #pragma unroll
    for (int e = 0; e < 8; e++)
        #pragma unroll
        for (int o = 16; o; o >>= 1)
            acc[e] += __shfl_xor_sync(0xffffffffu, acc[e], o);

    if (lane == 0) {
        float lg[8];
        #pragma unroll
        for (int e = 0; e < 8; e++) lg[e] = acc[e] + g3[e];

        int i1 = 0; float v1 = lg[0];
        #pragma unroll
        for (int e = 1; e < 8; e++)
            if (lg[e] > v1) { v1 = lg[e]; i1 = e; }
        int i2 = -1; float v2 = -3.4e38f;
        #pragma unroll
        for (int e = 0; e < 8; e++)
            if (e != i1 && lg[e] > v2) { v2 = lg[e]; i2 = e; }

        float ex = expf(v2 - v1);
        float p1 = 1.f / (1.f + ex);
        float p2 = ex  / (1.f + ex);

        float pr[8] = {0,0,0,0,0,0,0,0};
        pr[i1] = p1; pr[i2] = p2;
        float* prow = pout + (size_t)gw * NEXP;
        *(float4*)prow       = make_float4(pr[0], pr[1], pr[2], pr[3]);
        *(float4*)(prow + 4) = make_float4(pr[4], pr[5], pr[6], pr[7]);

        int s1 = atomicAdd(&g_cnt[i1], 1);
        g_list[i1 * NTOK + s1] = gw;
        g_wl  [i1 * NTOK + s1] = p1;
        int s2 = atomicAdd(&g_cnt[i2], 1);
        g_list[i2 * NTOK + s2] = gw;
        g_wl  [i2 * NTOK + s2] = p2;
    }
}

// ---------------- launch ----------------
extern "C" void kernel_launch(void* const* d_in, const int* in_sizes, int n_in,
                              void* d_out, int out_size)
{
    const float* x  = (const float*)d_in[0];
    const float* W1 = (const float*)d_in[1];
    const float* b1 = (const float*)d_in[2];
    const float* W2 = (const float*)d_in[3];
    const float* b2 = (const float*)d_in[4];
    const float* G1 = (const float*)d_in[5];
    const float* g1 = (const float*)d_in[6];
    const float* G2 = (const float*)d_in[7];
    const float* g2 = (const float*)d_in[8];
    const float* G3 = (const float*)d_in[9];
    const float* g3 = (const float*)d_in[10];

    float* y = (float*)d_out;
    float* p = (float*)d_out + (size_t)NTOK * OUTD;

    void* tmp;
    cudaGetSymbolAddress(&tmp, g_h1);   float* h1  = (float*)tmp;
    cudaGetSymbolAddress(&tmp, g_h2);   float* h2  = (float*)tmp;
    cudaGetSymbolAddress(&tmp, g_hid);  float* hid = (float*)tmp;
    cudaGetSymbolAddress(&tmp, g_list); int*   lst = (int*)tmp;
    cudaGetSymbolAddress(&tmp, g_cnt);  int*   cnt = (int*)tmp;
    cudaGetSymbolAddress(&tmp, g_wl);   float* wl  = (float*)tmp;

    cudaFuncSetAttribute(gemm_tc<0>, cudaFuncAttributeMaxDynamicSharedMemorySize, SMEM_BYTES);
    cudaFuncSetAttribute(gemm_tc<1>, cudaFuncAttributeMaxDynamicSharedMemorySize, SMEM_BYTES);

    reset_kernel<<<1, 32>>>();
    zero_y_kernel<<<(NTOK * OUTD) / (256 * 4), 256>>>(y);

    // gate layer 1: h1 = relu(x @ G1 + g1)   — tf32 3-term (selection-critical)
    gemm_tc<0><<<dim3(GH / 128, NTOK / 128, 1), 256, SMEM_BYTES>>>(
        x, 0, G1, 0, g1, 0, h1, 0, DIN, GH, 1, nullptr, nullptr, nullptr, nullptr);
    // gate layer 2: h2 = relu(h1 @ G2 + g2)  — tf32 3-term
    gemm_tc<0><<<dim3(DIN / 128, NTOK / 128, 1), 256, SMEM_BYTES>>>(
        h1, 0, G2, 0, g2, 0, h2, 0, GH, DIN, 1, nullptr, nullptr, nullptr, nullptr);
    // routing
    route_kernel<<<NTOK / 8, 256>>>(h2, G3, g3, p);
    // expert FFN1: hid[slot] = relu(x[list[slot]] @ W1[e] + b1[e])  — gather A
    gemm_tc<1><<<dim3(HID / 128, NTOK / 128, NEXP), 256, SMEM_BYTES>>>(
        x, 0, W1, (size_t)DIN * HID, b1, HID, hid, (size_t)NTOK * HID,
        DIN, HID, 1, lst, cnt, nullptr, nullptr);
    // expert FFN2 + fused combine: y[list[slot]] += wl[slot] * (hid[slot] @ W2[e] + b2[e])
    gemm_tc<1><<<dim3(OUTD / 128, NTOK / 128, NEXP), 256, SMEM_BYTES>>>(
        hid, (size_t)NTOK * HID, W2, (size_t)HID * OUTD, b2, OUTD, y, 0,
        HID, OUTD, 0, nullptr, cnt, lst, wl);
}

// round 13
// speedup vs baseline: 1.2846x; 1.0878x over previous
#include <cuda_runtime.h>
#include <math.h>
#include <stdint.h>

#define NTOK 8192
#define DIN  1024
#define NEXP 8
#define HID  4096
#define OUTD 1024
#define GH   4096
#define GAP_TH 2e-3f

// ---------------- scratch ----------------
__device__ float g_h1  [(size_t)NTOK * GH];
__device__ float g_h2  [(size_t)NTOK * DIN];
__device__ float g_hid [(size_t)NEXP * NTOK * HID];
__device__ float g_pout[(size_t)NEXP * NTOK * OUTD];
__device__ float g_lg  [NTOK * NEXP];
__device__ int   g_cnt [NEXP];
__device__ int   g_list[NEXP * NTOK];
__device__ int   g_slot[NTOK * 2];
__device__ float g_wt  [NTOK * 2];
__device__ int   g_flist[NTOK];
__device__ int   g_nf  [1];

__device__ __forceinline__ float tf32r(float x) {
    float r; asm("cvt.rna.tf32.f32 %0, %1;" : "=f"(r) : "f"(x)); return r;
}
__device__ __forceinline__ uint32_t cvta_s(const void* p) {
    uint32_t a;
    asm("{ .reg .u64 t; cvta.to.shared.u64 t, %1; cvt.u32.u64 %0, t; }" : "=r"(a) : "l"(p));
    return a;
}
#define CP16(d, s)  asm volatile("cp.async.ca.shared.global [%0], [%1], 16;" :: "r"(d), "l"(s))
#define CPCOMMIT()  asm volatile("cp.async.commit_group;" ::: "memory")
#define CPWAIT1()   asm volatile("cp.async.wait_group 1;" ::: "memory")

__device__ __forceinline__ void mma_tf32(float* c, const uint32_t* a, const uint32_t* b) {
    asm volatile(
        "mma.sync.aligned.m16n8k8.row.col.f32.tf32.tf32.f32 "
        "{%0,%1,%2,%3}, {%4,%5,%6,%7}, {%8,%9}, {%0,%1,%2,%3};\n"
        : "+f"(c[0]), "+f"(c[1]), "+f"(c[2]), "+f"(c[3])
        : "r"(a[0]), "r"(a[1]), "r"(a[2]), "r"(a[3]), "r"(b[0]), "r"(b[1]));
}
__device__ __forceinline__ void mma_bf16(float* c, const uint32_t* a, const uint32_t* b) {
    asm volatile(
        "mma.sync.aligned.m16n8k16.row.col.f32.bf16.bf16.f32 "
        "{%0,%1,%2,%3}, {%4,%5,%6,%7}, {%8,%9}, {%0,%1,%2,%3};\n"
        : "+f"(c[0]), "+f"(c[1]), "+f"(c[2]), "+f"(c[3])
        : "r"(a[0]), "r"(a[1]), "r"(a[2]), "r"(a[3]), "r"(b[0]), "r"(b[1]));
}
// exact 2-way bf16 split of a pair: hi = trunc16(v), mid holds residual; packed (x=lo, y=hi)
__device__ __forceinline__ void split2(float x, float y, uint32_t& hi, uint32_t& mid) {
    uint32_t ux = __float_as_uint(x), uy = __float_as_uint(y);
    hi = __byte_perm(ux, uy, 0x7632);
    float rx = x - __uint_as_float(ux & 0xFFFF0000u);
    float ry = y - __uint_as_float(uy & 0xFFFF0000u);
    mid = __byte_perm(__float_as_uint(rx), __float_as_uint(ry), 0x7632);
}

#define A_STRIDE 20
#define A_PLANE  (128 * A_STRIDE)
#define STAGE_F  (A_PLANE + 16 * 136)
#define NSTAGE   3
#define SMEM_BYTES (NSTAGE * STAGE_F * 4)  // 56832 -> 2 CTAs/SM

// ---------------- reset ----------------
__global__ void reset_kernel() {
    if (threadIdx.x < NEXP) g_cnt[threadIdx.x] = 0;
    if (threadIdx.x == 8) g_nf[0] = 0;
}

// ---------------- GEMM: C = (A @ B + bias)[relu], B row-major [K,N] ----------------
// MODE 0: tf32 3-term (exact repair path).  MODE 1: bf16 2-split 3-MMA (fast path).
// listA: gather map for A rows (indexed listA[e*listStride + row]); cntArr[e]: row count.
template<int MODE>
__global__ __launch_bounds__(256) void gemm_tc(
    const float* __restrict__ A, size_t sAe,
    const float* __restrict__ B, size_t sBe,
    const float* __restrict__ bias, size_t sBiasE,
    float* __restrict__ C, size_t sCe,
    int K, int N, int doRelu,
    const int* __restrict__ listA, int listStride,
    const int* __restrict__ cntArr)
{
    const int BSTR = MODE ? 132 : 136;
    const int e   = blockIdx.z;
    const int cnt = cntArr ? cntArr[e] : (int)(gridDim.y * 128);
    const int m0  = blockIdx.y * 128;
    if (m0 >= cnt) return;
    const int n0  = blockIdx.x * 128;

    extern __shared__ float smem[];
    const uint32_t sbase = cvta_s(smem);

    const int tid  = threadIdx.x;
    const int wid  = tid >> 5;
    const int lane = tid & 31;
    const int wm0  = (wid >> 2) * 64;
    const int wn0  = (wid & 3) * 32;

    int arow = m0 + (tid >> 1); if (arow > cnt - 1) arow = cnt - 1;
    if (listA) arow = listA[e * listStride + arow];
    const int acol = (tid & 1) * 8;
    const float* Ap = A + sAe * e + (size_t)arow * K + acol;
    const int bk = tid >> 4;
    const int bn = (tid & 15) * 8;
    const float* Bp = B + sBe * e + (size_t)bk * N + n0 + bn;
    const uint32_t adst0 = sbase + (uint32_t)((tid >> 1) * A_STRIDE + acol) * 4u;
    const uint32_t bdst0 = sbase + (uint32_t)(A_PLANE + bk * BSTR + bn) * 4u;

    const int T = K >> 4;

    auto issue = [&](int kt) {
        const int s = kt % NSTAGE;
        const float* ap = Ap + kt * 16;
        uint32_t ad = adst0 + (uint32_t)(s * STAGE_F) * 4u;
        CP16(ad,      ap);
        CP16(ad + 16, ap + 4);
        const float* bp = Bp + (size_t)kt * 16 * N;
        uint32_t bd = bdst0 + (uint32_t)(s * STAGE_F) * 4u;
        CP16(bd,      bp);
        CP16(bd + 16, bp + 4);
    };

    float acc[4][4][4];
    #pragma unroll
    for (int im = 0; im < 4; im++)
        #pragma unroll
        for (int jn = 0; jn < 4; jn++)
            #pragma unroll
            for (int q = 0; q < 4; q++) acc[im][jn][q] = 0.f;

    issue(0); CPCOMMIT();
    if (T > 1) issue(1);
    CPCOMMIT();

    const int fr = lane >> 2;
    const int fk = lane & 3;

    for (int kt = 0; kt < T; ++kt) {
        CPWAIT1();
        __syncthreads();
        const int s = kt % NSTAGE;
        const float* As_ = smem + s * STAGE_F;
        const float* Bs_ = smem + s * STAGE_F + A_PLANE;

        if (MODE == 1) {
            const int k2 = fk * 2;
            uint32_t ah[4][4], am[4][4];
            #pragma unroll
            for (int im = 0; im < 4; im++) {
                const int m = wm0 + im * 16 + fr;
                float2 v00 = *(const float2*)&As_[m * A_STRIDE + k2];
                float2 v10 = *(const float2*)&As_[(m + 8) * A_STRIDE + k2];
                float2 v01 = *(const float2*)&As_[m * A_STRIDE + k2 + 8];
                float2 v11 = *(const float2*)&As_[(m + 8) * A_STRIDE + k2 + 8];
                split2(v00.x, v00.y, ah[im][0], am[im][0]);
                split2(v10.x, v10.y, ah[im][1], am[im][1]);
                split2(v01.x, v01.y, ah[im][2], am[im][2]);
                split2(v11.x, v11.y, ah[im][3], am[im][3]);
            }
            uint32_t bh[4][2], bm[4][2];
            #pragma unroll
            for (int jn = 0; jn < 4; jn++) {
                const int n = wn0 + jn * 8 + fr;
                float b0 = Bs_[(k2)     * BSTR + n];
                float b1 = Bs_[(k2 + 1) * BSTR + n];
                float b2 = Bs_[(k2 + 8) * BSTR + n];
                float b3 = Bs_[(k2 + 9) * BSTR + n];
                split2(b0, b1, bh[jn][0], bm[jn][0]);
                split2(b2, b3, bh[jn][1], bm[jn][1]);
            }
            #pragma unroll
            for (int im = 0; im < 4; im++)
                #pragma unroll
                for (int jn = 0; jn < 4; jn++)
                    mma_bf16(acc[im][jn], ah[im], bh[jn]);
            #pragma unroll
            for (int im = 0; im < 4; im++)
                #pragma unroll
                for (int jn = 0; jn < 4; jn++)
                    mma_bf16(acc[im][jn], ah[im], bm[jn]);
            #pragma unroll
            for (int im = 0; im < 4; im++)
                #pragma unroll
                for (int jn = 0; jn < 4; jn++)
                    mma_bf16(acc[im][jn], am[im], bh[jn]);
        } else {
            #pragma unroll
            for (int ks = 0; ks < 16; ks += 8) {
                const int k = ks + fk;
                float arw[4][4];
                #pragma unroll
                for (int im = 0; im < 4; im++) {
                    const int m = wm0 + im * 16 + fr;
                    arw[im][0] = As_[m * A_STRIDE + k];
                    arw[im][1] = As_[(m + 8) * A_STRIDE + k];
                    arw[im][2] = As_[m * A_STRIDE + k + 4];
                    arw[im][3] = As_[(m + 8) * A_STRIDE + k + 4];
                }
                float brw[4][2];
                #pragma unroll
                for (int jn = 0; jn < 4; jn++) {
                    const int n = wn0 + jn * 8 + fr;
                    brw[jn][0] = Bs_[k * BSTR + n];
                    brw[jn][1] = Bs_[(k + 4) * BSTR + n];
                }
                uint32_t ah[4][4], al[4][4], bh[4][2], bl[4][2];
                #pragma unroll
                for (int im = 0; im < 4; im++)
                    #pragma unroll
                    for (int q = 0; q < 4; q++) {
                        float h = tf32r(arw[im][q]);
                        ah[im][q] = __float_as_uint(h);
                        al[im][q] = __float_as_uint(arw[im][q] - h);
                    }
                #pragma unroll
                for (int jn = 0; jn < 4; jn++)
                    #pragma unroll
                    for (int q = 0; q < 2; q++) {
                        float h = tf32r(brw[jn][q]);
                        bh[jn][q] = __float_as_uint(h);
                        bl[jn][q] = __float_as_uint(brw[jn][q] - h);
                    }
                #pragma unroll
                for (int im = 0; im < 4; im++)
                    #pragma unroll
                    for (int jn = 0; jn < 4; jn++)
                        mma_tf32(acc[im][jn], ah[im], bh[jn]);
                #pragma unroll
                for (int im = 0; im < 4; im++)
                    #pragma unroll
                    for (int jn = 0; jn < 4; jn++)
                        mma_tf32(acc[im][jn], ah[im], bl[jn]);
                #pragma unroll
                for (int im = 0; im < 4; im++)
                    #pragma unroll
                    for (int jn = 0; jn < 4; jn++)
                        mma_tf32(acc[im][jn], al[im], bh[jn]);
            }
        }

        if (kt + 2 < T) issue(kt + 2);
        CPCOMMIT();
    }

    // ---- epilogue: bias + relu + store ----
    const float* bp = bias + sBiasE * e + n0;
    float* Cbase = C + sCe * e;
    #pragma unroll
    for (int im = 0; im < 4; im++) {
        #pragma unroll
        for (int half = 0; half < 2; half++) {
            const int rr = m0 + wm0 + im * 16 + (lane >> 2) + half * 8;
            if (rr < cnt) {
                float* crow = Cbase + (size_t)rr * N + n0;
                #pragma unroll
                for (int jn = 0; jn < 4; jn++) {
                    const int col = wn0 + jn * 8 + (lane & 3) * 2;
                    float v0 = acc[im][jn][half * 2 + 0] + bp[col];
                    float v1 = acc[im][jn][half * 2 + 1] + bp[col + 1];
                    if (doRelu) { v0 = fmaxf(v0, 0.f); v1 = fmaxf(v1, 0.f); }
                    *(float2*)(crow + col) = make_float2(v0, v1);
                }
            }
        }
    }
}

// ---------------- warp dot: logits row from h2[row] ----------------
__device__ __forceinline__ void logits_dot(const float* __restrict__ hrow,
                                           const float* __restrict__ G3,
                                           const float* __restrict__ g3,
                                           int lane, float* lg)
{
    float acc[8] = {0,0,0,0,0,0,0,0};
    for (int k = lane; k < DIN; k += 32) {
        float hv = hrow[k];
        const float4 ga = *(const float4*)(G3 + k * 8);
        const float4 gb = *(const float4*)(G3 + k * 8 + 4);
        acc[0] += hv * ga.x; acc[1] += hv * ga.y;
        acc[2] += hv * ga.z; acc[3] += hv * ga.w;
        acc[4] += hv * gb.x; acc[5] += hv * gb.y;
        acc[6] += hv * gb.z; acc[7] += hv * gb.w;
    }
    #pragma unroll
    for (int e = 0; e < 8; e++) {
        #pragma unroll
        for (int o = 16; o; o >>= 1)
            acc[e] += __shfl_xor_sync(0xffffffffu, acc[e], o);
        lg[e] = acc[e] + g3[e];
    }
}

// ---------------- logits + near-tie flag (fast h2) ----------------
__global__ void logits_flag_kernel(const float* __restrict__ h2,
                                   const float* __restrict__ G3,
                                   const float* __restrict__ g3)
{
    const int tok  = (blockIdx.x * blockDim.x + threadIdx.x) >> 5;
    const int lane = threadIdx.x & 31;
    if (tok >= NTOK) return;
    float lg[8];
    logits_dot(h2 + (size_t)tok * DIN, G3, g3, lane, lg);
    if (lane == 0) {
        *(float4*)(g_lg + tok * 8)     = make_float4(lg[0], lg[1], lg[2], lg[3]);
        *(float4*)(g_lg + tok * 8 + 4) = make_float4(lg[4], lg[5], lg[6], lg[7]);
        float v1 = -3.4e38f, v2 = -3.4e38f, v3 = -3.4e38f;
        #pragma unroll
        for (int e = 0; e < 8; e++) {
            float v = lg[e];
            if (v > v1) { v3 = v2; v2 = v1; v1 = v; }
            else if (v > v2) { v3 = v2; v2 = v; }
            else if (v > v3) { v3 = v; }
        }
        if (v2 - v3 < GAP_TH) {
            int idx = atomicAdd(&g_nf[0], 1);
            g_flist[idx] = tok;
        }
    }
}

// ---------------- repaired logits (exact h2 for flagged slots) ----------------
__global__ void repair_logits_kernel(const float* __restrict__ h2r,
                                     const float* __restrict__ G3,
                                     const float* __restrict__ g3)
{
    const int slot = (blockIdx.x * blockDim.x + threadIdx.x) >> 5;
    const int lane = threadIdx.x & 31;
    if (slot >= g_nf[0]) return;
    const int tok = g_flist[slot];
    float lg[8];
    logits_dot(h2r + (size_t)slot * DIN, G3, g3, lane, lg);
    if (lane == 0) {
        *(float4*)(g_lg + tok * 8)     = make_float4(lg[0], lg[1], lg[2], lg[3]);
        *(float4*)(g_lg + tok * 8 + 4) = make_float4(lg[4], lg[5], lg[6], lg[7]);
    }
}

// ---------------- assign: top-2, softmax, p, expert lists ----------------
__global__ void assign_kernel(float* __restrict__ pout)
{
    __shared__ int scnt[NEXP];
    __shared__ int sbase[NEXP];
    const int tid = threadIdx.x;
    const int tok = blockIdx.x * blockDim.x + tid;
    if (tid < NEXP) scnt[tid] = 0;
    __syncthreads();

    float lg[8];
    *(float4*)(lg)     = *(const float4*)(g_lg + tok * 8);
    *(float4*)(lg + 4) = *(const float4*)(g_lg + tok * 8 + 4);

    int i1 = 0; float v1 = lg[0];
    #pragma unroll
    for (int e = 1; e < 8; e++)
        if (lg[e] > v1) { v1 = lg[e]; i1 = e; }
    int i2 = -1; float v2 = -3.4e38f;
    #pragma unroll
    for (int e = 0; e < 8; e++)
        if (e != i1 && lg[e] > v2) { v2 = lg[e]; i2 = e; }

    float ex = expf(v2 - v1);
    float p1 = 1.f / (1.f + ex);
    float p2 = ex  / (1.f + ex);

    float pr[8] = {0,0,0,0,0,0,0,0};
    pr[i1] = p1; pr[i2] = p2;
    *(float4*)(pout + (size_t)tok * 8)     = make_float4(pr[0], pr[1], pr[2], pr[3]);
    *(float4*)(pout + (size_t)tok * 8 + 4) = make_float4(pr[4], pr[5], pr[6], pr[7]);

    const int o1 = atomicAdd(&scnt[i1], 1);
    const int o2 = atomicAdd(&scnt[i2], 1);
    __syncthreads();
    if (tid < NEXP) sbase[tid] = atomicAdd(&g_cnt[tid], scnt[tid]);
    __syncthreads();

    const int s1 = sbase[i1] + o1;
    g_list[i1 * NTOK + s1] = tok;
    g_slot[tok * 2 + 0] = i1 * NTOK + s1;
    g_wt  [tok * 2 + 0] = p1;
    const int s2 = sbase[i2] + o2;
    g_list[i2 * NTOK + s2] = tok;
    g_slot[tok * 2 + 1] = i2 * NTOK + s2;
    g_wt  [tok * 2 + 1] = p2;
}

// ---------------- combine ----------------
__global__ void combine_kernel(float* __restrict__ y)
{
    const int t = blockIdx.x;
    const int c = threadIdx.x * 4;
    const int s0 = g_slot[t * 2 + 0];
    const int s1 = g_slot[t * 2 + 1];
    const float w0 = g_wt[t * 2 + 0];
    const float w1 = g_wt[t * 2 + 1];
    float4 a = *(const float4*)(g_pout + (size_t)s0 * OUTD + c);
    float4 b = *(const float4*)(g_pout + (size_t)s1 * OUTD + c);
    float4 rr;
    rr.x = w0 * a.x + w1 * b.x;
    rr.y = w0 * a.y + w1 * b.y;
    rr.z = w0 * a.z + w1 * b.z;
    rr.w = w0 * a.w + w1 * b.w;
    *(float4*)(y + (size_t)t * OUTD + c) = rr;
}

// ---------------- launch ----------------
extern "C" void kernel_launch(void* const* d_in, const int* in_sizes, int n_in,
                              void* d_out, int out_size)
{
    const float* x  = (const float*)d_in[0];
    const float* W1 = (const float*)d_in[1];
    const float* b1 = (const float*)d_in[2];
    const float* W2 = (const float*)d_in[3];
    const float* b2 = (const float*)d_in[4];
    const float* G1 = (const float*)d_in[5];
    const float* g1 = (const float*)d_in[6];
    const float* G2 = (const float*)d_in[7];
    const float* g2 = (const float*)d_in[8];
    const float* G3 = (const float*)d_in[9];
    const float* g3 = (const float*)d_in[10];

    float* y = (float*)d_out;
    float* p = (float*)d_out + (size_t)NTOK * OUTD;

    void* tmp;
    cudaGetSymbolAddress(&tmp, g_h1);    float* h1  = (float*)tmp;
    cudaGetSymbolAddress(&tmp, g_h2);    float* h2  = (float*)tmp;
    cudaGetSymbolAddress(&tmp, g_hid);   float* hid = (float*)tmp;
    cudaGetSymbolAddress(&tmp, g_pout);  float* po  = (float*)tmp;
    cudaGetSymbolAddress(&tmp, g_list);  int*   lst = (int*)tmp;
    cudaGetSymbolAddress(&tmp, g_cnt);   int*   cnt = (int*)tmp;
    cudaGetSymbolAddress(&tmp, g_flist); int*   fls = (int*)tmp;
    cudaGetSymbolAddress(&tmp, g_nf);    int*   nf  = (int*)tmp;

    cudaFuncSetAttribute(gemm_tc<0>, cudaFuncAttributeMaxDynamicSharedMemorySize, SMEM_BYTES);
    cudaFuncSetAttribute(gemm_tc<1>, cudaFuncAttributeMaxDynamicSharedMemorySize, SMEM_BYTES);

    reset_kernel<<<1, 32>>>();

    // fast gates (bf16 2-split): h1 = relu(x@G1+g1), h2 = relu(h1@G2+g2)
    gemm_tc<1><<<dim3(GH / 128, NTOK / 128, 1), 256, SMEM_BYTES>>>(
        x, 0, G1, 0, g1, 0, h1, 0, DIN, GH, 1, nullptr, 0, nullptr);
    gemm_tc<1><<<dim3(DIN / 128, NTOK / 128, 1), 256, SMEM_BYTES>>>(
        h1, 0, G2, 0, g2, 0, h2, 0, GH, DIN, 1, nullptr, 0, nullptr);
    // logits + near-tie flagging
    logits_flag_kernel<<<NTOK / 8, 256>>>(h2, G3, g3);
    // exact repair of flagged tokens (tf32 3-term, gathered; early-exit capacity grid)
    gemm_tc<0><<<dim3(GH / 128, NTOK / 128, 1), 256, SMEM_BYTES>>>(
        x, 0, G1, 0, g1, 0, h1, 0, DIN, GH, 1, fls, 0, nf);
    gemm_tc<0><<<dim3(DIN / 128, NTOK / 128, 1), 256, SMEM_BYTES>>>(
        h1, 0, G2, 0, g2, 0, h2, 0, GH, DIN, 1, nullptr, 0, nf);
    repair_logits_kernel<<<NTOK / 8, 256>>>(h2, G3, g3);
    // final routing from corrected logits
    assign_kernel<<<NTOK / 256, 256>>>(p);
    // expert FFN1: hid[slot] = relu(x[list[e][slot]] @ W1[e] + b1[e])
    gemm_tc<1><<<dim3(HID / 128, NTOK / 128, NEXP), 256, SMEM_BYTES>>>(
        x, 0, W1, (size_t)DIN * HID, b1, HID, hid, (size_t)NTOK * HID,
        DIN, HID, 1, lst, NTOK, cnt);
    // expert FFN2: pout = hid @ W2[e] + b2[e]
    gemm_tc<1><<<dim3(OUTD / 128, NTOK / 128, NEXP), 256, SMEM_BYTES>>>(
        hid, (size_t)NTOK * HID, W2, (size_t)HID * OUTD, b2, OUTD, po, (size_t)NTOK * OUTD,
        HID, OUTD, 0, nullptr, 0, cnt);
    // weighted combine
    combine_kernel<<<NTOK, 256>>>(y);
}